// round 3
// baseline (speedup 1.0000x reference)
#include <cuda_runtime.h>
#include <cuda_bf16.h>

// InfoNCE loss (fused gather + dot + log-softmax + mean).
//   inputs: embeddings f32 [100000,128], targets i32 [16384],
//           contexts i32 [16384], negatives i32 [16384,20]
//   output: scalar f32 loss
//
// One warp per batch element; lane l holds float4 [4l,4l+4) of each row
// (coalesced 512B warp gathers). Online softmax over 3 chunks of 7 logits
// keeps live registers low -> 6 blocks/SM (48 warps) for latency hiding.

#define BATCH   16384
#define DIM     128
#define NUM_NEG 20
#define NLOGITS (NUM_NEG + 1)
#define CHUNK   7
#define INV_T   (1.0f / 0.07f)

__global__ void zero_kernel(float* out) {
    out[0] = 0.0f;
}

__global__ __launch_bounds__(256, 6) void infonce_kernel(
    const float* __restrict__ emb,
    const int* __restrict__ targets,
    const int* __restrict__ contexts,
    const int* __restrict__ negatives,
    float* __restrict__ out)
{
    const int lane = threadIdx.x & 31;
    const int warp_in_blk = threadIdx.x >> 5;
    const int b = (blockIdx.x << 3) + warp_in_blk;

    float loss = 0.0f;
    if (b < BATCH) {
        const float4* __restrict__ e4 = (const float4*)emb;

        // target row: lane l -> elements [4l, 4l+4)
        const float4 t = e4[(size_t)targets[b] * 32 + lane];

        // indices: context + 20 negatives (5x int4 uniform broadcast loads)
        int idx[NLOGITS];
        idx[0] = contexts[b];
        const int4* __restrict__ n4 = (const int4*)(negatives + b * NUM_NEG);
        #pragma unroll
        for (int j = 0; j < 5; j++) {
            const int4 q = n4[j];
            idx[4 * j + 1] = q.x;
            idx[4 * j + 2] = q.y;
            idx[4 * j + 3] = q.z;
            idx[4 * j + 4] = q.w;
        }

        float m = -__int_as_float(0x7f800000);  // -inf
        float sum = 0.0f;
        float pos = 0.0f;

        #pragma unroll
        for (int c = 0; c < NLOGITS / CHUNK; c++) {
            // 7 gathered partial dots (7 LDG.128 in flight per lane)
            float s[CHUNK];
            #pragma unroll
            for (int k = 0; k < CHUNK; k++) {
                const float4 v = e4[(size_t)idx[c * CHUNK + k] * 32 + lane];
                s[k] = fmaf(t.x, v.x, fmaf(t.y, v.y, fmaf(t.z, v.z, t.w * v.w)));
            }
            // butterfly-reduce each logit across the warp
            #pragma unroll
            for (int k = 0; k < CHUNK; k++) {
                float x = s[k];
                x += __shfl_xor_sync(0xFFFFFFFFu, x, 16);
                x += __shfl_xor_sync(0xFFFFFFFFu, x, 8);
                x += __shfl_xor_sync(0xFFFFFFFFu, x, 4);
                x += __shfl_xor_sync(0xFFFFFFFFu, x, 2);
                x += __shfl_xor_sync(0xFFFFFFFFu, x, 1);
                s[k] = x * INV_T;
            }
            if (c == 0) pos = s[0];

            // online max/sum update
            float cm = s[0];
            #pragma unroll
            for (int k = 1; k < CHUNK; k++) cm = fmaxf(cm, s[k]);
            const float nm = fmaxf(m, cm);
            float cs = 0.0f;
            #pragma unroll
            for (int k = 0; k < CHUNK; k++) cs += __expf(s[k] - nm);
            sum = sum * __expf(m - nm) + cs;   // exp(-inf)=0 handles c==0
            m = nm;
        }

        loss = (m + __logf(sum) - pos) * (1.0f / (float)BATCH);
    }

    // block reduce: 8 warps -> smem -> one red.add per block
    __shared__ float part[8];
    if (lane == 0) part[warp_in_blk] = loss;
    __syncthreads();
    if (threadIdx.x == 0) {
        float tot = 0.0f;
        #pragma unroll
        for (int w = 0; w < 8; w++) tot += part[w];
        atomicAdd(out, tot);
    }
}

extern "C" void kernel_launch(void* const* d_in, const int* in_sizes, int n_in,
                              void* d_out, int out_size) {
    const float* emb = (const float*)d_in[0];
    const int*   tgt = (const int*)d_in[1];
    const int*   ctx = (const int*)d_in[2];
    const int*   neg = (const int*)d_in[3];
    float* out = (float*)d_out;

    zero_kernel<<<1, 1>>>(out);

    const int blocks = BATCH / 8;  // 2048 blocks x 256 threads (8 warps)
    infonce_kernel<<<blocks, 256>>>(emb, tgt, ctx, neg, out);
}

// round 4
// speedup vs baseline: 1.2297x; 1.2297x over previous
#include <cuda_runtime.h>
#include <cuda_bf16.h>

// InfoNCE loss (fused gather + dot + log-softmax + mean).
//   inputs: embeddings f32 [100000,128], targets i32 [16384],
//           contexts i32 [16384], negatives i32 [16384,20]
//   output: scalar f32 loss
//
// One warp per batch element; lane l holds float4 [4l,4l+4) of each row
// (coalesced 512B warp gathers). All 21 logits are reduced across the warp
// with a multi-value transpose butterfly: 31 shuffles total instead of 105,
// leaving lane l with fully-reduced logit bitrev5(l). Softmax then costs one
// exp per lane + 10 shuffles instead of 21 redundant exps per lane.

#define BATCH   16384
#define NUM_NEG 20
#define NLOGITS (NUM_NEG + 1)
#define INV_T   (1.0f / 0.07f)
#define FULL    0xFFFFFFFFu

__global__ void zero_kernel(float* out) {
    out[0] = 0.0f;
}

__global__ __launch_bounds__(256) void infonce_kernel(
    const float* __restrict__ emb,
    const int* __restrict__ targets,
    const int* __restrict__ contexts,
    const int* __restrict__ negatives,
    float* __restrict__ out)
{
    const int lane = threadIdx.x & 31;
    const int warp_in_blk = threadIdx.x >> 5;
    const int b = (blockIdx.x << 3) + warp_in_blk;

    const float4* __restrict__ e4 = (const float4*)emb;

    // target row: lane l -> elements [4l, 4l+4)
    const float4 t = e4[(size_t)targets[b] * 32 + lane];

    // indices: context + 20 negatives (5x int4 broadcast loads)
    int idx[NLOGITS];
    idx[0] = contexts[b];
    const int4* __restrict__ n4 = (const int4*)(negatives + b * NUM_NEG);
    #pragma unroll
    for (int j = 0; j < 5; j++) {
        const int4 q = n4[j];
        idx[4 * j + 1] = q.x;
        idx[4 * j + 2] = q.y;
        idx[4 * j + 3] = q.z;
        idx[4 * j + 4] = q.w;
    }

    // 21 gathered per-lane partial dots (unrolled -> loads batch up)
    float val[32];
    #pragma unroll
    for (int k = 0; k < NLOGITS; k++) {
        const float4 v = e4[(size_t)idx[k] * 32 + lane];
        val[k] = fmaf(t.x, v.x, fmaf(t.y, v.y, fmaf(t.z, v.z, t.w * v.w)));
    }
    #pragma unroll
    for (int k = NLOGITS; k < 32; k++) val[k] = 0.0f;

    // Multi-value transpose butterfly: at stage with mask m, pair
    // (val[2i], val[2i+1]); keep your own, send the other, add what the
    // xor-partner sends. After 5 stages lane l holds the warp-summed logit
    // with index bitrev5(l).
    #pragma unroll
    for (int m = 16; m >= 1; m >>= 1) {
        #pragma unroll
        for (int i = 0; i < m; i++) {
            const float a = val[2 * i];
            const float c = val[2 * i + 1];
            const bool hi = (lane & m) != 0;
            const float keep = hi ? c : a;
            const float sent = hi ? a : c;
            val[i] = keep + __shfl_xor_sync(FULL, sent, m);
        }
    }

    const float x = val[0] * INV_T;                 // logit bitrev5(lane)
    const int logit_id = (int)(__brev((unsigned)lane) >> 27);
    const bool valid = logit_id < NLOGITS;

    // warp max over valid lanes
    float xm = valid ? x : -__int_as_float(0x7f800000);
    #pragma unroll
    for (int o = 16; o >= 1; o >>= 1)
        xm = fmaxf(xm, __shfl_xor_sync(FULL, xm, o));

    // warp sum of exp
    float e = valid ? __expf(x - xm) : 0.0f;
    #pragma unroll
    for (int o = 16; o >= 1; o >>= 1)
        e += __shfl_xor_sync(FULL, e, o);

    const float pos = __shfl_sync(FULL, x, 0);      // lane 0 holds logit 0
    const float loss = (xm + __logf(e) - pos) * (1.0f / (float)BATCH);

    // block reduce: 8 warps -> smem -> one atomic per block
    __shared__ float part[8];
    if (lane == 0) part[warp_in_blk] = loss;
    __syncthreads();
    if (threadIdx.x == 0) {
        float tot = 0.0f;
        #pragma unroll
        for (int w = 0; w < 8; w++) tot += part[w];
        atomicAdd(out, tot);
    }
}

extern "C" void kernel_launch(void* const* d_in, const int* in_sizes, int n_in,
                              void* d_out, int out_size) {
    const float* emb = (const float*)d_in[0];
    const int*   tgt = (const int*)d_in[1];
    const int*   ctx = (const int*)d_in[2];
    const int*   neg = (const int*)d_in[3];
    float* out = (float*)d_out;

    zero_kernel<<<1, 1>>>(out);

    const int blocks = BATCH / 8;  // 2048 blocks x 256 threads (8 warps)
    infonce_kernel<<<blocks, 256>>>(emb, tgt, ctx, neg, out);
}